// round 17
// baseline (speedup 1.0000x reference)
#include <cuda_runtime.h>
#include <cuda_bf16.h>
#include <math.h>
#include <stdint.h>

#define N_ROWS 8192
#define K_CODES 8192
#define DIM 256
#define NSPLIT 64                 // col-tiles of 128
#define TAU 2.5e-3f
#define FIXEPS 2.5e-3f

// ---------------- scratch (__device__ statics: no allocation) ----------------
__device__ float g_zn[N_ROWS * DIM];
__device__ float g_en[K_CODES * DIM];
__device__ float g_en2[K_CODES];
__device__ __nv_bfloat16 g_zh[N_ROWS * DIM];
__device__ __nv_bfloat16 g_eh[K_CODES * DIM];
__device__ float g_pT1[NSPLIT * N_ROWS];
__device__ float g_pT2[NSPLIT * N_ROWS];
__device__ int   g_pI1[NSPLIT * N_ROWS];
__device__ int   g_idx[N_ROWS];
__device__ float g_ap[K_CODES];          // unnormalized column sums U_k
__device__ int   g_counts[K_CODES];
__device__ float g_commit[1];
__device__ int   g_fixCnt[1];
__device__ int   g_fixList[N_ROWS];
__device__ int   g_tileCnt[NSPLIT];
__device__ int   g_tileRows[(size_t)NSPLIT * N_ROWS];   // per-tile candidate row lists
__device__ unsigned long long g_best[N_ROWS];

#define OFF_IDX  (N_ROWS * DIM)
#define OFF_LOSS (OFF_IDX + N_ROWS)
#define OFF_PERP (OFF_LOSS + 1)

// ---------------- helpers ----------------
__device__ __forceinline__ uint32_t smem_u32(const void* p) {
    uint32_t a;
    asm("{ .reg .u64 t; cvta.to.shared.u64 t, %1; cvt.u32.u64 %0, t; }" : "=r"(a) : "l"(p));
    return a;
}
__device__ __forceinline__ void cp_async16(uint32_t dst, const void* src) {
    asm volatile("cp.async.cg.shared.global [%0], [%1], 16;" :: "r"(dst), "l"(src));
}
__device__ __forceinline__ void cp_commit() { asm volatile("cp.async.commit_group;"); }
__device__ __forceinline__ void cp_wait1()  { asm volatile("cp.async.wait_group 1;"); }
__device__ __forceinline__ void cp_wait0()  { asm volatile("cp.async.wait_group 0;"); }

__device__ __forceinline__ void ldsm4(uint32_t* r, uint32_t addr) {
    asm volatile("ldmatrix.sync.aligned.m8n8.x4.shared.b16 {%0,%1,%2,%3}, [%4];"
        : "=r"(r[0]), "=r"(r[1]), "=r"(r[2]), "=r"(r[3]) : "r"(addr));
}
__device__ __forceinline__ void mma_bf16(float* d, const uint32_t* a, const uint32_t* b) {
    asm volatile(
        "mma.sync.aligned.m16n8k16.row.col.f32.bf16.bf16.f32 "
        "{%0,%1,%2,%3}, {%4,%5,%6,%7}, {%8,%9}, {%0,%1,%2,%3};"
        : "+f"(d[0]), "+f"(d[1]), "+f"(d[2]), "+f"(d[3])
        : "r"(a[0]), "r"(a[1]), "r"(a[2]), "r"(a[3]), "r"(b[0]), "r"(b[1]));
}

// order-preserving (key, lowest-idx-wins) packing for atomicMax
__device__ __forceinline__ unsigned long long packKey(float key, int idx) {
    uint32_t b = __float_as_uint(key);
    b = (b & 0x80000000u) ? ~b : (b | 0x80000000u);
    return ((unsigned long long)b << 32) | (uint32_t)(~idx);
}

// smem layout (dynamic): 2 stages x (A 16KB + B 16KB) = 64KB, aux 512B, comb 8KB
#define STAGE 32768
#define BOFF  16384
#define AUXS  65536
#define COMBS 66048
#define SMEMT (66048 + 8192)

// ---------------------------------------------------------------------------
// one warp per row: L2-normalize + bf16 round
__device__ __forceinline__ void norm_row(const float* src, float* dst,
                                         __nv_bfloat16* dh, int row, int lane, float* ss_out) {
    float4 v0 = reinterpret_cast<const float4*>(src)[lane * 2];
    float4 v1 = reinterpret_cast<const float4*>(src)[lane * 2 + 1];
    float ss = v0.x*v0.x + v0.y*v0.y + v0.z*v0.z + v0.w*v0.w
             + v1.x*v1.x + v1.y*v1.y + v1.z*v1.z + v1.w*v1.w;
#pragma unroll
    for (int o = 16; o; o >>= 1) ss += __shfl_xor_sync(0xffffffffu, ss, o);
    float sc = 1.f / fmaxf(sqrtf(ss), 1e-12f);
    v0.x *= sc; v0.y *= sc; v0.z *= sc; v0.w *= sc;
    v1.x *= sc; v1.y *= sc; v1.z *= sc; v1.w *= sc;
    reinterpret_cast<float4*>(dst)[lane * 2]     = v0;
    reinterpret_cast<float4*>(dst)[lane * 2 + 1] = v1;
    float vv[8] = {v0.x, v0.y, v0.z, v0.w, v1.x, v1.y, v1.z, v1.w};
    alignas(16) __nv_bfloat16 hh[8];
#pragma unroll
    for (int i = 0; i < 8; i++) hh[i] = __float2bfloat16(vv[i]);
    *reinterpret_cast<uint4*>(dh + (size_t)row * DIM + lane * 8) = *reinterpret_cast<uint4*>(hh);
    *ss_out = ss * sc * sc;
}

// fused: normalize z + emb, zero ap/counts/tileCnt/scalars
__global__ void norm_all_kernel(const float* __restrict__ z, const float* __restrict__ emb) {
    int gid = blockIdx.x * blockDim.x + threadIdx.x;
    if (gid < K_CODES) { g_ap[gid] = 0.f; g_counts[gid] = 0; }
    if (gid < NSPLIT) g_tileCnt[gid] = 0;
    if (gid == 0) { g_commit[0] = 0.f; g_fixCnt[0] = 0; }
    int w = gid >> 5;
    int lane = threadIdx.x & 31;
    if (w >= N_ROWS + K_CODES) return;
    if (w < N_ROWS) {
        float dummy;
        norm_row(z + (size_t)w * DIM, g_zn + (size_t)w * DIM, g_zh, w, lane, &dummy);
    } else {
        int row = w - N_ROWS;
        float e2;
        norm_row(emb + (size_t)row * DIM, g_en + (size_t)row * DIM, g_eh, row, lane, &e2);
        if (lane == 0) g_en2[row] = e2;
    }
}

// ---------------------------------------------------------------------------
// one K-chunk (64) of A (128 z rows) + B (128 e rows) into stage buffer
__device__ __forceinline__ void issue_stage(uint32_t sb, int stage, int kc,
                                            int row0, int col0, int t) {
    uint32_t base = sb + stage * STAGE;
#pragma unroll
    for (int i = 0; i < 4; i++) {
        int v = i * 256 + t;
        int r = v >> 3, gg = v & 7;
        cp_async16(base + (uint32_t)(r * 128 + (((gg ^ (r & 7)) & 7) << 4)),
                   g_zh + (size_t)(row0 + r) * DIM + kc * 64 + gg * 8);
    }
#pragma unroll
    for (int i = 0; i < 4; i++) {
        int v = i * 256 + t;
        int r = v >> 3, gg = v & 7;
        cp_async16(base + BOFF + (uint32_t)(r * 128 + (((gg ^ (r & 7)) & 7) << 4)),
                   g_eh + (size_t)(col0 + r) * DIM + kc * 64 + gg * 8);
    }
    cp_commit();
}

// shared ldmatrix mainloop: fills acc[2][8][4] for this CTA tile
__device__ __forceinline__ void gemm_mainloop(uint32_t sb, int row0, int col0, int t,
                                              int wm, int wn, int lane,
                                              float acc[2][8][4]) {
    const int halfA = lane >> 4;
    const int subA  = (lane >> 3) & 1;
    const int rrA   = lane & 7;
    const int quadB = lane >> 3;
    const int rrB   = lane & 7;

    int rowA[2], maskA[2];
#pragma unroll
    for (int m = 0; m < 2; m++) {
        rowA[m] = wm * 32 + m * 16 + subA * 8 + rrA;
        maskA[m] = rowA[m] & 7;
    }
    int rowB[4], maskB[4];
#pragma unroll
    for (int np = 0; np < 4; np++) {
        rowB[np] = wn * 64 + (2 * np + (quadB >> 1)) * 8 + rrB;
        maskB[np] = rowB[np] & 7;
    }

    issue_stage(sb, 0, 0, row0, col0, t);
    for (int kc = 0; kc < 4; kc++) {
        if (kc < 3) issue_stage(sb, (kc + 1) & 1, kc + 1, row0, col0, t);
        if (kc < 3) cp_wait1(); else cp_wait0();
        __syncthreads();
        uint32_t Ab = sb + (kc & 1) * STAGE;
        uint32_t Bb = Ab + BOFF;
        uint32_t baseA0 = Ab + rowA[0] * 128, baseA1 = Ab + rowA[1] * 128;
        uint32_t baseB[4];
#pragma unroll
        for (int np = 0; np < 4; np++) baseB[np] = Bb + rowB[np] * 128;
#pragma unroll
        for (int ks = 0; ks < 4; ks++) {
            int gA = ks * 2 + halfA;
            int gB = ks * 2 + (quadB & 1);
            uint32_t a[2][4], bq[4][4];
            ldsm4(a[0], baseA0 + (((gA ^ maskA[0]) & 7) << 4));
            ldsm4(a[1], baseA1 + (((gA ^ maskA[1]) & 7) << 4));
#pragma unroll
            for (int np = 0; np < 4; np++)
                ldsm4(bq[np], baseB[np] + (((gB ^ maskB[np]) & 7) << 4));
#pragma unroll
            for (int m = 0; m < 2; m++)
#pragma unroll
                for (int np = 0; np < 4; np++) {
                    mma_bf16(acc[m][2 * np],     a[m], &bq[np][0]);
                    mma_bf16(acc[m][2 * np + 1], a[m], &bq[np][2]);
                }
        }
        __syncthreads();
    }
}

// ---------------------------------------------------------------------------
// single GEMM pass: top1/top2 key partials + unnormalized column e-sums -> g_ap
__global__ void __launch_bounds__(256, 2) gemm1_kernel() {
    extern __shared__ char smem[];
    const uint32_t sb = smem_u32(smem);
    const int t = threadIdx.x, w = t >> 5, lane = t & 31;
    const int wm = w & 3, wn = w >> 2;
    const int lrow = lane >> 2, kq = (lane & 3) * 2;
    const int row0 = blockIdx.x * 128;
    const int col0 = blockIdx.y * 128;

    float acc[2][8][4];
#pragma unroll
    for (int m = 0; m < 2; m++)
#pragma unroll
        for (int n = 0; n < 8; n++)
#pragma unroll
            for (int c = 0; c < 4; c++) acc[m][n][c] = 0.f;

    if (t < 128) *(float*)(smem + AUXS + t * 4) = g_en2[col0 + t];

    gemm_mainloop(sb, row0, col0, t, wm, wn, lane, acc);

    const float* sE2 = (const float*)(smem + AUXS);
    float* sT1 = (float*)(smem + COMBS);            // 256 f
    float* sT2 = sT1 + 256;                         // 256 f
    int*   sI1 = (int*)(sT2 + 256);                 // 256 i
    float (*sCol)[64] = (float (*)[64])(sI1 + 256); // 8 x 64 f

    float colAcc[8][2];
#pragma unroll
    for (int n = 0; n < 8; n++) { colAcc[n][0] = 0.f; colAcc[n][1] = 0.f; }

#pragma unroll
    for (int m = 0; m < 2; m++)
#pragma unroll
        for (int rh = 0; rh < 2; rh++) {
            int rloc = wm * 32 + m * 16 + rh * 8 + lrow;
            float t1 = -3.4e38f, t2 = -3.4e38f;
            int i1 = 0x7fffffff;
#pragma unroll
            for (int n = 0; n < 8; n++) {
                int cl = wn * 64 + n * 8 + kq;
                float s0 = acc[m][n][rh * 2 + 0];
                float s1 = acc[m][n][rh * 2 + 1];
                float k0 = fmaf(2.f, s0, -sE2[cl]);
                float k1 = fmaf(2.f, s1, -sE2[cl + 1]);
                colAcc[n][0] += __expf(-20.f * s0);
                colAcc[n][1] += __expf(-20.f * s1);
                int g0 = col0 + cl, g1 = g0 + 1;
                if (k0 > t1 || (k0 == t1 && g0 < i1)) { t2 = t1; t1 = k0; i1 = g0; } else t2 = fmaxf(t2, k0);
                if (k1 > t1 || (k1 == t1 && g1 < i1)) { t2 = t1; t1 = k1; i1 = g1; } else t2 = fmaxf(t2, k1);
            }
#pragma unroll
            for (int off = 1; off <= 2; off <<= 1) {
                float ok = __shfl_xor_sync(0xffffffffu, t1, off);
                int   oi = __shfl_xor_sync(0xffffffffu, i1, off);
                float o2 = __shfl_xor_sync(0xffffffffu, t2, off);
                if (ok > t1 || (ok == t1 && oi < i1)) { t2 = fmaxf(t1, o2); t1 = ok; i1 = oi; }
                else t2 = fmaxf(t2, ok);
            }
            if ((lane & 3) == 0) {
                int slot = rloc * 2 + wn;
                sT1[slot] = t1; sT2[slot] = t2; sI1[slot] = i1;
            }
        }
    // column e-sum reduce over the 8 lrow lanes
#pragma unroll
    for (int off = 4; off <= 16; off <<= 1)
#pragma unroll
        for (int n = 0; n < 8; n++) {
            colAcc[n][0] += __shfl_xor_sync(0xffffffffu, colAcc[n][0], off);
            colAcc[n][1] += __shfl_xor_sync(0xffffffffu, colAcc[n][1], off);
        }
    if (lane < 4) {
#pragma unroll
        for (int n = 0; n < 8; n++) {
            sCol[w][n * 8 + lane * 2]     = colAcc[n][0];
            sCol[w][n * 8 + lane * 2 + 1] = colAcc[n][1];
        }
    }
    __syncthreads();
    if (t < 128) {
        float a1 = sT1[t * 2], a2 = sT2[t * 2];         int ai = sI1[t * 2];
        float b1 = sT1[t * 2 + 1], b2 = sT2[t * 2 + 1]; int bi = sI1[t * 2 + 1];
        float T1, T2; int I1;
        if (b1 > a1 || (b1 == a1 && bi < ai)) { T1 = b1; I1 = bi; T2 = fmaxf(a1, b2); }
        else                                  { T1 = a1; I1 = ai; T2 = fmaxf(b1, a2); }
        int g = blockIdx.y * N_ROWS + row0 + t;
        g_pT1[g] = T1; g_pT2[g] = T2; g_pI1[g] = I1;
        int wn2 = t >> 6, c = t & 63;
        float tot = sCol[wn2 * 4 + 0][c] + sCol[wn2 * 4 + 1][c]
                  + sCol[wn2 * 4 + 2][c] + sCol[wn2 * 4 + 3][c];
        atomicAdd(&g_ap[col0 + wn2 * 64 + c], tot);
    }
}

// ---------------------------------------------------------------------------
// combine: global top1/top2; ambiguous rows append to per-tile candidate lists
__global__ void combine_kernel() {
    int r = blockIdx.x * blockDim.x + threadIdx.x;
    if (r >= N_ROWS) return;
    float T1 = -3.4e38f, T2 = -3.4e38f;
    int I1 = 0x7fffffff;
    for (int s = 0; s < NSPLIT; s++) {
        float a1 = g_pT1[s * N_ROWS + r], a2 = g_pT2[s * N_ROWS + r];
        int ai = g_pI1[s * N_ROWS + r];
        if (a1 > T1 || (a1 == T1 && ai < I1)) { T2 = fmaxf(T1, a2); T1 = a1; I1 = ai; }
        else T2 = fmaxf(T2, a1);
    }
    g_idx[r] = I1;
    if (T1 - T2 < TAU) {
        int p = atomicAdd(&g_fixCnt[0], 1);
        g_fixList[p] = r;
        g_best[r] = 0ull;
        float thresh = T1 - FIXEPS;
        for (int s = 0; s < NSPLIT; s++) {
            if (g_pT1[s * N_ROWS + r] >= thresh) {
                int q = atomicAdd(&g_tileCnt[s], 1);
                g_tileRows[(size_t)s * N_ROWS + q] = r;
            }
        }
    }
}

// ---------------------------------------------------------------------------
// tile-major exact rescore: block = tile; cache 32 z-rows in smem, stream e once.
// thread (rloc = t&31, cg = t>>5): full-precision dot of row rloc vs 16 codes.
__global__ void fixex_kernel() {
    __shared__ float sz[32][260];        // pad 4 floats: conflict-free LDS.128
    __shared__ int srow[32];
    int t = threadIdx.x;
    int tile = blockIdx.x;
    int R = g_tileCnt[tile];
    int code0 = tile * 128;
    for (int chunk = 0; chunk < R; chunk += 32) {
        int nr = min(32, R - chunk);
        __syncthreads();
        if (t < nr) srow[t] = g_tileRows[(size_t)tile * N_ROWS + chunk + t];
        __syncthreads();
        for (int i = t; i < nr * 64; i += 256) {
            int ri = i >> 6, v = i & 63;
            *reinterpret_cast<float4*>(&sz[ri][v * 4]) =
                reinterpret_cast<const float4*>(g_zn + (size_t)srow[ri] * DIM)[v];
        }
        __syncthreads();
        int rloc = t & 31, cg = t >> 5;
        if (rloc < nr) {
            unsigned long long best = 0ull;
            for (int cc = 0; cc < 16; cc++) {
                int c = code0 + cg * 16 + cc;
                const float4* e = reinterpret_cast<const float4*>(g_en + (size_t)c * DIM);
                float s = 0.f;
#pragma unroll 8
                for (int v = 0; v < 64; v++) {
                    float4 ev = e[v];
                    float4 zv = *reinterpret_cast<const float4*>(&sz[rloc][v * 4]);
                    s += ev.x * zv.x + ev.y * zv.y + ev.z * zv.z + ev.w * zv.w;
                }
                float key = fmaf(2.f, s, -g_en2[c]);
                unsigned long long pk = packKey(key, c);
                if (pk > best) best = pk;
            }
            atomicMax(&g_best[srow[rloc]], best);
        }
    }
}

// unpack exact winners into g_idx
__global__ void fix3_kernel() {
    int i = blockIdx.x * blockDim.x + threadIdx.x;
    if (i < g_fixCnt[0]) {
        int r = g_fixList[i];
        g_idx[r] = (int)(~(uint32_t)(g_best[r] & 0xffffffffull));
    }
}

// ---------------------------------------------------------------------------
__global__ void zq_kernel(float* __restrict__ out) {
    __shared__ float sC[8];
    int n = (blockIdx.x * blockDim.x + threadIdx.x) >> 5;
    int w = threadIdx.x >> 5;
    int lane = threadIdx.x & 31;
    int idx = g_idx[n];
    const float4* e  = reinterpret_cast<const float4*>(g_en + (size_t)idx * DIM);
    const float4* zr = reinterpret_cast<const float4*>(g_zn + (size_t)n * DIM);
    float4* o = reinterpret_cast<float4*>(out + (size_t)n * DIM);
    float4 e0 = e[lane * 2], e1 = e[lane * 2 + 1];
    float4 z0 = zr[lane * 2], z1 = zr[lane * 2 + 1];
    o[lane * 2] = e0; o[lane * 2 + 1] = e1;
    float dx, ss = 0.f;
    dx = e0.x - z0.x; ss += dx * dx;  dx = e0.y - z0.y; ss += dx * dx;
    dx = e0.z - z0.z; ss += dx * dx;  dx = e0.w - z0.w; ss += dx * dx;
    dx = e1.x - z1.x; ss += dx * dx;  dx = e1.y - z1.y; ss += dx * dx;
    dx = e1.z - z1.z; ss += dx * dx;  dx = e1.w - z1.w; ss += dx * dx;
#pragma unroll
    for (int o2 = 16; o2; o2 >>= 1) ss += __shfl_xor_sync(0xffffffffu, ss, o2);
    if (lane == 0) {
        sC[w] = ss;
        atomicAdd(&g_counts[idx], 1);
        out[OFF_IDX + n] = (float)idx;
    }
    __syncthreads();
    if (threadIdx.x == 0) {
        float s = 0.f;
#pragma unroll
        for (int ww = 0; ww < 8; ww++) s += sC[ww];
        atomicAdd(&g_commit[0], s);
    }
}

// finalize: normalize U_k, diversity + commit + perplexity
__global__ void finalize_kernel(float* __restrict__ out) {
    __shared__ float sred[256];
    int t = threadIdx.x;
    float su = 0.f;
    for (int k = t; k < K_CODES; k += 256) su += g_ap[k];
    sred[t] = su;
    __syncthreads();
    for (int s = 128; s; s >>= 1) {
        if (t < s) sred[t] += sred[t + s];
        __syncthreads();
    }
    float invS = 1.f / sred[0];
    __syncthreads();
    __shared__ float sdiv[256], sperp[256];
    float dv = 0.f, pp = 0.f;
    for (int k = t; k < K_CODES; k += 256) {
        float p = g_ap[k] * invS;
        dv += p * logf(p);
        float pr = (float)g_counts[k] * (1.0f / (float)N_ROWS);
        pp += pr * logf(pr + 1e-10f);
    }
    sdiv[t] = dv; sperp[t] = pp;
    __syncthreads();
    for (int s = 128; s; s >>= 1) {
        if (t < s) { sdiv[t] += sdiv[t + s]; sperp[t] += sperp[t + s]; }
        __syncthreads();
    }
    if (t == 0) {
        float commit = 1.25f * g_commit[0] / (float)(N_ROWS * DIM);
        out[OFF_LOSS] = commit + sdiv[0];
        out[OFF_PERP] = expf(-sperp[0]);
    }
}

// ---------------------------------------------------------------------------
extern "C" void kernel_launch(void* const* d_in, const int* in_sizes, int n_in,
                              void* d_out, int out_size) {
    const float* z   = (const float*)d_in[0];
    const float* emb = (const float*)d_in[1];
    float* out = (float*)d_out;

    cudaFuncSetAttribute(gemm1_kernel, cudaFuncAttributeMaxDynamicSharedMemorySize, SMEMT);

    norm_all_kernel<<<(N_ROWS + K_CODES) / 8, 256>>>(z, emb);              // 1 (also zeroes ap/counts/tileCnt/scalars)
    gemm1_kernel<<<dim3(N_ROWS / 128, K_CODES / 128), 256, SMEMT>>>();     // 2
    combine_kernel<<<N_ROWS / 256, 256>>>();                               // 3
    fixex_kernel<<<NSPLIT, 256>>>();                                       // 4 (profiled)
    fix3_kernel<<<N_ROWS / 256, 256>>>();                                  // 5
    zq_kernel<<<N_ROWS / 8, 256>>>(out);                                   // 6
    finalize_kernel<<<1, 256>>>(out);                                      // 7
}